// round 2
// baseline (speedup 1.0000x reference)
#include <cuda_runtime.h>
#include <math.h>

#define N_NODES 4096
#define IN_F    512
#define OUT_F   64
#define HEADS   8
#define ALPHA   0.2f
#define NEG_BIG (-9000000000000000.0f)

// Scratch (allocation-free contract: __device__ globals)
__device__ float g_Wh [HEADS * N_NODES * OUT_F];   // 8 MB
__device__ float g_Wh1[HEADS * N_NODES];
__device__ float g_Wh2[HEADS * N_NODES];

// ---------------------------------------------------------------------------
// Kernel A: Wh[h] = h @ W[h]  (4096x512 @ 512x64), fused Wh1/Wh2 epilogue.
// Grid (64, 8), 256 threads, 64x64 tile, 4x4 micro-tile, K-chunk 32.
// ---------------------------------------------------------------------------
__global__ __launch_bounds__(256) void wh_kernel(const float* __restrict__ h,
                                                 const float* __restrict__ W,
                                                 const float* __restrict__ a)
{
    __shared__ float hT[32][68];   // [k][n], transposed, padded (16B-aligned rows)
    __shared__ float wS[32][64];   // [k][o]
    __shared__ float a1s[64], a2s[64];

    const int t    = threadIdx.x;
    const int tx   = t & 15;       // 0..15 -> o-dir
    const int ty   = t >> 4;       // 0..15 -> n-dir
    const int n0   = blockIdx.x * 64;
    const int head = blockIdx.y;

    if (t < 64)        a1s[t]      = a[head * 128 + t];
    else if (t < 128)  a2s[t - 64] = a[head * 128 + t];

    float acc[4][4] = {};
    const float* Wb = W + head * IN_F * OUT_F;

    for (int k0 = 0; k0 < IN_F; k0 += 32) {
        __syncthreads();
        // h tile -> transposed smem. rows r = t/8 (+0,+32), cols c4 = (t%8)*4
        {
            const int r  = t >> 3;
            const int c4 = (t & 7) << 2;
            #pragma unroll
            for (int rb = 0; rb < 64; rb += 32) {
                float4 v = *(const float4*)(h + (size_t)(n0 + r + rb) * IN_F + k0 + c4);
                hT[c4 + 0][r + rb] = v.x;
                hT[c4 + 1][r + rb] = v.y;
                hT[c4 + 2][r + rb] = v.z;
                hT[c4 + 3][r + rb] = v.w;
            }
        }
        // W tile: kk = ty (+0,+16), o4 = tx*4
        {
            const int o4 = tx << 2;
            #pragma unroll
            for (int kb = 0; kb < 32; kb += 16) {
                *(float4*)&wS[ty + kb][o4] =
                    *(const float4*)(Wb + (size_t)(k0 + ty + kb) * OUT_F + o4);
            }
        }
        __syncthreads();
        #pragma unroll
        for (int kk = 0; kk < 32; kk++) {
            float4 av = *(const float4*)&hT[kk][ty << 2];
            float4 bv = *(const float4*)&wS[kk][tx << 2];
            acc[0][0] += av.x * bv.x; acc[0][1] += av.x * bv.y;
            acc[0][2] += av.x * bv.z; acc[0][3] += av.x * bv.w;
            acc[1][0] += av.y * bv.x; acc[1][1] += av.y * bv.y;
            acc[1][2] += av.y * bv.z; acc[1][3] += av.y * bv.w;
            acc[2][0] += av.z * bv.x; acc[2][1] += av.z * bv.y;
            acc[2][2] += av.z * bv.z; acc[2][3] += av.z * bv.w;
            acc[3][0] += av.w * bv.x; acc[3][1] += av.w * bv.y;
            acc[3][2] += av.w * bv.z; acc[3][3] += av.w * bv.w;
        }
    }

    // Store Wh tile
    float* whp = g_Wh + ((size_t)head * N_NODES + n0) * OUT_F;
    #pragma unroll
    for (int i = 0; i < 4; i++) {
        const int r = (ty << 2) + i;
        float4 v = make_float4(acc[i][0], acc[i][1], acc[i][2], acc[i][3]);
        *(float4*)(whp + (size_t)r * OUT_F + (tx << 2)) = v;
    }

    // Fused Wh1/Wh2: per-row dot with a1/a2, reduce across the 16 tx lanes
    #pragma unroll
    for (int i = 0; i < 4; i++) {
        float p1 = 0.f, p2 = 0.f;
        #pragma unroll
        for (int j = 0; j < 4; j++) {
            const int o = (tx << 2) + j;
            p1 += acc[i][j] * a1s[o];
            p2 += acc[i][j] * a2s[o];
        }
        #pragma unroll
        for (int off = 8; off >= 1; off >>= 1) {
            p1 += __shfl_xor_sync(0xffffffffu, p1, off);
            p2 += __shfl_xor_sync(0xffffffffu, p2, off);
        }
        if (tx == 0) {
            const int n = n0 + (ty << 2) + i;
            g_Wh1[head * N_NODES + n] = p1;
            g_Wh2[head * N_NODES + n] = p2;
        }
    }
}

// ---------------------------------------------------------------------------
// Kernel B: fused masked attention + aggregation GEMM + ELU.
// out[n][head*64+o] = elu( sum_m attn(n,m) * Wh[head][m][o] )
// attn(n,m) = adj[n,m]>0 ? leaky_relu(Wh1[n]+Wh2[m]) : NEG_BIG
// Grid (32, 8), 256 threads, 128(n) x 64(o) tile, 8x4 micro, m-chunk 32.
// ---------------------------------------------------------------------------
__global__ __launch_bounds__(256) void attn_kernel(const int* __restrict__ adj,
                                                   float* __restrict__ out)
{
    __shared__ float attT[32][132];  // [m][n] transposed attention, 16B-aligned rows
    __shared__ float whS[32][64];    // [m][o]
    __shared__ float wh1s[128];
    __shared__ float wh2s[32];

    const int t    = threadIdx.x;
    const int tx   = t & 15;   // o-dir
    const int ty   = t >> 4;   // n-dir
    const int n0   = blockIdx.x * 128;
    const int head = blockIdx.y;

    if (t < 128) wh1s[t] = g_Wh1[head * N_NODES + n0 + t];

    float acc[8][4] = {};
    const float* whp = g_Wh + (size_t)head * N_NODES * OUT_F;

    for (int m0 = 0; m0 < N_NODES; m0 += 32) {
        __syncthreads();  // previous-iter consumers done; wh1s visible (iter 0)

        if (t < 32) wh2s[t] = g_Wh2[head * N_NODES + m0 + t];

        // Wh tile: mm = ty (+0,+16), o4 = tx*4
        {
            const int o4 = tx << 2;
            #pragma unroll
            for (int mb = 0; mb < 32; mb += 16) {
                *(float4*)&whS[ty + mb][o4] =
                    *(const float4*)(whp + (size_t)(m0 + ty + mb) * OUT_F + o4);
            }
        }

        // adj tile into registers: rows r = t/8 (+0,32,64,96), cols m4 = (t%8)*4
        int4 av[4];
        const int r  = t >> 3;
        const int m4 = (t & 7) << 2;
        #pragma unroll
        for (int q = 0; q < 4; q++)
            av[q] = *(const int4*)(adj + (size_t)(n0 + r + q * 32) * N_NODES + m0 + m4);

        __syncthreads();  // wh2s ready

        // Compute transposed attention tile
        #pragma unroll
        for (int q = 0; q < 4; q++) {
            const int rr = r + q * 32;
            const float w1 = wh1s[rr];
            int vals[4] = {av[q].x, av[q].y, av[q].z, av[q].w};
            #pragma unroll
            for (int c = 0; c < 4; c++) {
                float s = w1 + wh2s[m4 + c];
                float e = s > 0.f ? s : ALPHA * s;
                attT[m4 + c][rr] = (vals[c] > 0) ? e : NEG_BIG;
            }
        }
        __syncthreads();

        // Inner FMA loop: 3x LDS.128 + 32x FFMA per mm
        #pragma unroll
        for (int mm = 0; mm < 32; mm++) {
            float4 b   = *(const float4*)&whS[mm][tx << 2];
            float4 a0  = *(const float4*)&attT[mm][ty << 3];
            float4 a1v = *(const float4*)&attT[mm][(ty << 3) + 4];
            acc[0][0] += a0.x * b.x;  acc[0][1] += a0.x * b.y;
            acc[0][2] += a0.x * b.z;  acc[0][3] += a0.x * b.w;
            acc[1][0] += a0.y * b.x;  acc[1][1] += a0.y * b.y;
            acc[1][2] += a0.y * b.z;  acc[1][3] += a0.y * b.w;
            acc[2][0] += a0.z * b.x;  acc[2][1] += a0.z * b.y;
            acc[2][2] += a0.z * b.z;  acc[2][3] += a0.z * b.w;
            acc[3][0] += a0.w * b.x;  acc[3][1] += a0.w * b.y;
            acc[3][2] += a0.w * b.z;  acc[3][3] += a0.w * b.w;
            acc[4][0] += a1v.x * b.x; acc[4][1] += a1v.x * b.y;
            acc[4][2] += a1v.x * b.z; acc[4][3] += a1v.x * b.w;
            acc[5][0] += a1v.y * b.x; acc[5][1] += a1v.y * b.y;
            acc[5][2] += a1v.y * b.z; acc[5][3] += a1v.y * b.w;
            acc[6][0] += a1v.z * b.x; acc[6][1] += a1v.z * b.y;
            acc[6][2] += a1v.z * b.z; acc[6][3] += a1v.z * b.w;
            acc[7][0] += a1v.w * b.x; acc[7][1] += a1v.w * b.y;
            acc[7][2] += a1v.w * b.z; acc[7][3] += a1v.w * b.w;
        }
    }

    // Epilogue: ELU + store to out[n][head*64 + o]
    #pragma unroll
    for (int i = 0; i < 8; i++) {
        const int n = n0 + (ty << 3) + i;
        float4 v;
        float* pv = &v.x;
        #pragma unroll
        for (int j = 0; j < 4; j++) {
            float x = acc[i][j];
            pv[j] = (x > 0.f) ? x : (expf(x) - 1.0f);
        }
        *(float4*)(out + (size_t)n * (HEADS * OUT_F) + head * OUT_F + (tx << 2)) = v;
    }
}

extern "C" void kernel_launch(void* const* d_in, const int* in_sizes, int n_in,
                              void* d_out, int out_size)
{
    const float* h   = (const float*)d_in[0];   // [4096, 512] f32
    const int*   adj = (const int*)  d_in[1];   // [4096, 4096] i32
    const float* W   = (const float*)d_in[2];   // [8, 512, 64] f32
    const float* a   = (const float*)d_in[3];   // [8, 128, 1] f32
    float*       out = (float*)d_out;           // [4096, 512] f32

    (void)in_sizes; (void)n_in; (void)out_size;

    dim3 gA(N_NODES / 64, HEADS);
    wh_kernel<<<gA, 256>>>(h, W, a);

    dim3 gB(N_NODES / 128, HEADS);
    attn_kernel<<<gB, 256>>>(adj, out);
}

// round 4
// speedup vs baseline: 1.6588x; 1.6588x over previous
#include <cuda_runtime.h>
#include <cuda_bf16.h>
#include <math.h>
#include <stdint.h>

#define N_NODES 4096
#define IN_F    512
#define OUT_F   64
#define HEADS   8
#define ALPHA   0.2f
#define NEG_BIG (-9000000000000000.0f)

// ---------------- scratch (allocation-free contract) ----------------
__device__ float         g_Wh [HEADS * N_NODES * OUT_F];          // 8 MB fp32
__device__ float         g_Wh1[HEADS * N_NODES];
__device__ float         g_Wh2[HEADS * N_NODES];
__device__ float         g_T  [HEADS * OUT_F];                    // column sums
// B operands, tiled: element (head, m, o) at ((head*512 + m/8)*64 + o)*8 + m%8
__device__ __nv_bfloat16 g_Bhi[(size_t)HEADS * 512 * 64 * 8];     // 4 MB
__device__ __nv_bfloat16 g_Blo[(size_t)HEADS * 512 * 64 * 8];     // 4 MB
__device__ uint32_t      g_adjbits[(size_t)N_NODES * (N_NODES / 32)]; // 2 MB

// ---------------- helpers ----------------
__device__ __forceinline__ uint32_t smem_to_u32(const void* p) {
    uint32_t a;
    asm("{ .reg .u64 t; cvta.to.shared.u64 t, %1; cvt.u32.u64 %0, t; }" : "=r"(a) : "l"(p));
    return a;
}
__device__ __forceinline__ void ldm4(uint32_t* r, uint32_t addr) {
    asm volatile("ldmatrix.sync.aligned.m8n8.x4.shared.b16 {%0,%1,%2,%3}, [%4];"
        : "=r"(r[0]), "=r"(r[1]), "=r"(r[2]), "=r"(r[3]) : "r"(addr));
}
__device__ __forceinline__ void mma16816(float* c, const uint32_t* a, const uint32_t* b) {
    asm volatile("mma.sync.aligned.m16n8k16.row.col.f32.bf16.bf16.f32 "
        "{%0,%1,%2,%3}, {%4,%5,%6,%7}, {%8,%9}, {%0,%1,%2,%3};"
        : "+f"(c[0]), "+f"(c[1]), "+f"(c[2]), "+f"(c[3])
        : "r"(a[0]), "r"(a[1]), "r"(a[2]), "r"(a[3]), "r"(b[0]), "r"(b[1]));
}
__device__ __forceinline__ uint32_t pack_bf16x2(float lo, float hi) {
    uint32_t d;
    asm("cvt.rn.bf16x2.f32 %0, %1, %2;" : "=r"(d) : "f"(hi), "f"(lo));
    return d;
}

// ---------------------------------------------------------------------------
// Kernel A: Wh[h] = h @ W[h], fused Wh1/Wh2.  (fp32, proven in R2)
// ---------------------------------------------------------------------------
__global__ __launch_bounds__(256) void wh_kernel(const float* __restrict__ h,
                                                 const float* __restrict__ W,
                                                 const float* __restrict__ a)
{
    __shared__ float hT[32][68];
    __shared__ float wS[32][64];
    __shared__ float a1s[64], a2s[64];

    const int t    = threadIdx.x;
    const int tx   = t & 15;
    const int ty   = t >> 4;
    const int n0   = blockIdx.x * 64;
    const int head = blockIdx.y;

    if (t < 64)        a1s[t]      = a[head * 128 + t];
    else if (t < 128)  a2s[t - 64] = a[head * 128 + t];

    float acc[4][4] = {};
    const float* Wb = W + head * IN_F * OUT_F;

    for (int k0 = 0; k0 < IN_F; k0 += 32) {
        __syncthreads();
        {
            const int r  = t >> 3;
            const int c4 = (t & 7) << 2;
            #pragma unroll
            for (int rb = 0; rb < 64; rb += 32) {
                float4 v = *(const float4*)(h + (size_t)(n0 + r + rb) * IN_F + k0 + c4);
                hT[c4 + 0][r + rb] = v.x;
                hT[c4 + 1][r + rb] = v.y;
                hT[c4 + 2][r + rb] = v.z;
                hT[c4 + 3][r + rb] = v.w;
            }
        }
        {
            const int o4 = tx << 2;
            #pragma unroll
            for (int kb = 0; kb < 32; kb += 16) {
                *(float4*)&wS[ty + kb][o4] =
                    *(const float4*)(Wb + (size_t)(k0 + ty + kb) * OUT_F + o4);
            }
        }
        __syncthreads();
        #pragma unroll
        for (int kk = 0; kk < 32; kk++) {
            float4 av = *(const float4*)&hT[kk][ty << 2];
            float4 bv = *(const float4*)&wS[kk][tx << 2];
            acc[0][0] += av.x * bv.x; acc[0][1] += av.x * bv.y;
            acc[0][2] += av.x * bv.z; acc[0][3] += av.x * bv.w;
            acc[1][0] += av.y * bv.x; acc[1][1] += av.y * bv.y;
            acc[1][2] += av.y * bv.z; acc[1][3] += av.y * bv.w;
            acc[2][0] += av.z * bv.x; acc[2][1] += av.z * bv.y;
            acc[2][2] += av.z * bv.z; acc[2][3] += av.z * bv.w;
            acc[3][0] += av.w * bv.x; acc[3][1] += av.w * bv.y;
            acc[3][2] += av.w * bv.z; acc[3][3] += av.w * bv.w;
        }
    }

    float* whp = g_Wh + ((size_t)head * N_NODES + n0) * OUT_F;
    #pragma unroll
    for (int i = 0; i < 4; i++) {
        const int r = (ty << 2) + i;
        float4 v = make_float4(acc[i][0], acc[i][1], acc[i][2], acc[i][3]);
        *(float4*)(whp + (size_t)r * OUT_F + (tx << 2)) = v;
    }

    #pragma unroll
    for (int i = 0; i < 4; i++) {
        float p1 = 0.f, p2 = 0.f;
        #pragma unroll
        for (int j = 0; j < 4; j++) {
            const int o = (tx << 2) + j;
            p1 += acc[i][j] * a1s[o];
            p2 += acc[i][j] * a2s[o];
        }
        #pragma unroll
        for (int off = 8; off >= 1; off >>= 1) {
            p1 += __shfl_xor_sync(0xffffffffu, p1, off);
            p2 += __shfl_xor_sync(0xffffffffu, p2, off);
        }
        if (tx == 0) {
            const int n = n0 + (ty << 2) + i;
            g_Wh1[head * N_NODES + n] = p1;
            g_Wh2[head * N_NODES + n] = p2;
        }
    }
}

// ---------------------------------------------------------------------------
// Kernel A2: pack adj into bitmask. 524288 words, coalesced.
// ---------------------------------------------------------------------------
__global__ __launch_bounds__(256) void adjbits_kernel(const int* __restrict__ adj)
{
    const size_t idx = (size_t)blockIdx.x * 256 + threadIdx.x;
    const int* p = adj + idx * 32;
    uint32_t w = 0;
    #pragma unroll
    for (int q = 0; q < 8; q++) {
        int4 v = *(const int4*)(p + q * 4);
        w |= (v.x > 0 ? 1u : 0u) << (q * 4 + 0);
        w |= (v.y > 0 ? 1u : 0u) << (q * 4 + 1);
        w |= (v.z > 0 ? 1u : 0u) << (q * 4 + 2);
        w |= (v.w > 0 ? 1u : 0u) << (q * 4 + 3);
    }
    g_adjbits[idx] = w;
}

// ---------------------------------------------------------------------------
// Kernel A3: per head — Wh -> tiled bf16 hi/lo B layout + column sums T.
// Grid 8 blocks, 512 threads: thread = (o = tid&63, rq = tid>>6).
// ---------------------------------------------------------------------------
__global__ __launch_bounds__(512) void prep_kernel()
{
    __shared__ float ps[8][64];
    const int head = blockIdx.x;
    const int o  = threadIdx.x & 63;
    const int rq = threadIdx.x >> 6;

    const float* src = g_Wh + (size_t)head * N_NODES * OUT_F;

    float s = 0.f;
    for (int r0 = rq * 512; r0 < rq * 512 + 512; r0 += 8) {
        uint32_t hp[4], lp[4];
        #pragma unroll
        for (int j = 0; j < 8; j += 2) {
            float x0 = src[(size_t)(r0 + j) * OUT_F + o];
            float x1 = src[(size_t)(r0 + j + 1) * OUT_F + o];
            s += x0 + x1;
            __nv_bfloat16 h0 = __float2bfloat16(x0);
            __nv_bfloat16 h1 = __float2bfloat16(x1);
            float l0f = x0 - __bfloat162float(h0);
            float l1f = x1 - __bfloat162float(h1);
            hp[j >> 1] = (uint32_t)__bfloat16_as_ushort(h0) |
                         ((uint32_t)__bfloat16_as_ushort(h1) << 16);
            lp[j >> 1] = pack_bf16x2(l0f, l1f);
        }
        const size_t g = (size_t)(head * 512 + (r0 >> 3)) * 64 + o;
        *(uint4*)(g_Bhi + g * 8) = *(uint4*)hp;
        *(uint4*)(g_Blo + g * 8) = *(uint4*)lp;
    }
    ps[rq][o] = s;
    __syncthreads();
    if (rq == 0) {
        float t = 0.f;
        #pragma unroll
        for (int q = 0; q < 8; q++) t += ps[q][o];
        g_T[head * OUT_F + o] = t;
    }
}

// ---------------------------------------------------------------------------
// Kernel B: fused masked-attention aggregation via mma.sync (bf16 HMMA).
//   M[n,o] = adj @ (Bhi + Blo)  (shared f32 accumulator, exact products)
//   E[n,o] = P   @ Bhi          (P = adj ? lrelu(Wh1[n]+Wh2[m]) : 0)
//   out    = elu( NEG_BIG*(T[o]-M) + E )
// Block: 128 n x 64 o, one head. 256 threads = 8 warps (16 n-rows each).
// m-chunk 32, double-buffered smem, ldmatrix-friendly 80B row stride.
// ---------------------------------------------------------------------------
// smem (dynamic): [0..512) wh1s, [512..768) tTs, buffers at 1024.
// per-buffer (30720 B): adj[128][40] (10240) | p (10240) | bhi[64][40] (5120) | blo (5120)
#define BUF_SZ   30720
#define ADJ_OFF  1024
#define P_REL    10240
#define BHI_REL  20480
#define BLO_REL  25600
#define SMEM_B_BYTES (ADJ_OFF + 2 * BUF_SZ)

__global__ __launch_bounds__(256, 2) void attn_mma_kernel(float* __restrict__ out)
{
    extern __shared__ char smem[];
    const uint32_t smem_u = smem_to_u32(smem);
    const int tid  = threadIdx.x;
    const int wid  = tid >> 5;
    const int lane = tid & 31;
    const int n0   = blockIdx.x * 128;
    const int head = blockIdx.y;

    float* wh1s = (float*)(smem);
    float* tTs  = (float*)(smem + 512);

    if (tid < 128)               wh1s[tid]       = g_Wh1[head * N_NODES + n0 + tid];
    if (tid >= 128 && tid < 192) tTs[tid - 128]  = g_T[head * OUT_F + (tid - 128)];
    __syncthreads();

    // ---- build-role mapping ----
    const int r    = tid & 127;          // A-tile row
    const int half = tid >> 7;           // 0/1
    const int j0   = half << 4;          // m offset 0/16 within chunk
    const float w1 = wh1s[r];
    const uint32_t offA = (uint32_t)r * 80 + (uint32_t)j0 * 2;
    const int bo = tid & 63;             // B-tile row (o)
    const int bq = tid >> 6;             // 0..3 -> 8 m each
    const uint32_t offB = (uint32_t)bo * 80 + (uint32_t)bq * 16;
    const uint32_t* bitrow = g_adjbits + (size_t)(n0 + r) * (N_NODES / 32);
    const float* w2base = g_Wh2 + head * N_NODES + j0;
    const __nv_bfloat16* bhiH = g_Bhi + (size_t)head * 512 * 64 * 8;
    const __nv_bfloat16* bloH = g_Blo + (size_t)head * 512 * 64 * 8;

    // ---- mma-role mapping ----
    const int wrow = wid * 16;
    const uint32_t aLd = (uint32_t)(wrow + (lane & 15)) * 80 + (uint32_t)(lane >> 4) * 16;
    const uint32_t bLd0 = (uint32_t)((lane & 7) + ((lane >> 4) & 1) * 8) * 80
                        + (uint32_t)((lane >> 3) & 1) * 16;

    float cM[8][4] = {};
    float cE[8][4] = {};

    // ---- build helper (inlined twice via macro) ----
    #define BUILD_TILES(CHUNK, BUF, BITS32) do {                                   \
        const uint32_t _bb = ADJ_OFF + (BUF) * BUF_SZ;                             \
        /* B tiles (coalesced LDG, 16B STS) */                                     \
        {                                                                          \
            const size_t _gi = ((size_t)(4 * (CHUNK) + bq) * 64 + bo) * 8;         \
            uint4 hv = *(const uint4*)(bhiH + _gi);                                \
            uint4 lv = *(const uint4*)(bloH + _gi);                                \
            *(uint4*)(smem + _bb + BHI_REL + offB) = hv;                           \
            *(uint4*)(smem + _bb + BLO_REL + offB) = lv;                           \
        }                                                                          \
        /* A tiles: adj indicator + P */                                           \
        {                                                                          \
            const uint32_t _bits = (BITS32) >> j0;                                 \
            const float4* _w2p = (const float4*)(w2base + (CHUNK) * 32);           \
            uint32_t _apk[8], _ppk[8];                                             \
            _Pragma("unroll")                                                      \
            for (int _q = 0; _q < 4; _q++) {                                       \
                float4 w2 = _w2p[_q];                                              \
                const uint32_t b0 = (_bits >> (_q * 4 + 0)) & 1u;                  \
                const uint32_t b1 = (_bits >> (_q * 4 + 1)) & 1u;                  \
                const uint32_t b2 = (_bits >> (_q * 4 + 2)) & 1u;                  \
                const uint32_t b3 = (_bits >> (_q * 4 + 3)) & 1u;                  \
                _apk[_q * 2 + 0] = (b0 ? 0x00003F80u : 0u) | (b1 ? 0x3F800000u : 0u); \
                _apk[_q * 2 + 1] = (b2 ? 0x00003F80u : 0u) | (b3 ? 0x3F800000u : 0u); \
                float s0 = w1 + w2.x, s1 = w1 + w2.y;                              \
                float s2 = w1 + w2.z, s3 = w1 + w2.w;                              \
                float p0 = b0 ? (s0 > 0.f ? s0 : ALPHA * s0) : 0.f;                \
                float p1 = b1 ? (s1 > 0.f ? s1 : ALPHA * s1) : 0.f;                \
                float p2 = b2 ? (s2 > 0.f ? s2 : ALPHA * s2) : 0.f;                \
                float p3 = b3 ? (s3 > 0.f ? s3 : ALPHA * s3) : 0.f;                \
                _ppk[_q * 2 + 0] = pack_bf16x2(p0, p1);                            \
                _ppk[_q * 2 + 1] = pack_bf16x2(p2, p3);                            \
            }                                                                      \
            *(uint4*)(smem + _bb + offA)              = *(uint4*)(_apk + 0);       \
            *(uint4*)(smem + _bb + offA + 16)         = *(uint4*)(_apk + 4);       \
            *(uint4*)(smem + _bb + P_REL + offA)      = *(uint4*)(_ppk + 0);       \
            *(uint4*)(smem + _bb + P_REL + offA + 16) = *(uint4*)(_ppk + 4);       \
        }                                                                          \
    } while (0)

    uint4 bw = *(const uint4*)(bitrow);           // words for chunks 0..3
    BUILD_TILES(0, 0, bw.x);
    __syncthreads();

    for (int c = 0; c < 128; c++) {
        const int cur = c & 1;
        const int nc = c + 1;
        if (nc < 128) {
            if ((nc & 3) == 0) bw = *(const uint4*)(bitrow + nc);
            const uint32_t w = (nc & 3) == 0 ? bw.x :
                               (nc & 3) == 1 ? bw.y :
                               (nc & 3) == 2 ? bw.z : bw.w;
            BUILD_TILES(nc, 1 - cur, w);
        }

        // ---- MMA phase on buffer cur ----
        const uint32_t bufB = smem_u + ADJ_OFF + cur * BUF_SZ;
        #pragma unroll
        for (int ks = 0; ks < 2; ks++) {
            uint32_t aA[4], aP[4];
            ldm4(aA, bufB + aLd + ks * 32);
            ldm4(aP, bufB + P_REL + aLd + ks * 32);
            #pragma unroll
            for (int t4 = 0; t4 < 4; t4++) {
                uint32_t bh[4], bl[4];
                const uint32_t bOff = bLd0 + (uint32_t)t4 * 1280 + ks * 32;
                ldm4(bh, bufB + BHI_REL + bOff);
                mma16816(cM[2 * t4 + 0], aA, bh + 0);
                mma16816(cM[2 * t4 + 1], aA, bh + 2);
                mma16816(cE[2 * t4 + 0], aP, bh + 0);
                mma16816(cE[2 * t4 + 1], aP, bh + 2);
                ldm4(bl, bufB + BLO_REL + bOff);
                mma16816(cM[2 * t4 + 0], aA, bl + 0);
                mma16816(cM[2 * t4 + 1], aA, bl + 2);
            }
        }
        __syncthreads();
    }

    // ---- epilogue ----
    const int gid = lane >> 2;
    const int tig = lane & 3;
    const int row0 = n0 + wrow + gid;
    #pragma unroll
    for (int j = 0; j < 8; j++) {
        const int o0 = 8 * j + 2 * tig;
        const float t0 = tTs[o0], t1 = tTs[o0 + 1];
        float x00 = NEG_BIG * (t0 - cM[j][0]) + cE[j][0];
        float x01 = NEG_BIG * (t1 - cM[j][1]) + cE[j][1];
        float x10 = NEG_BIG * (t0 - cM[j][2]) + cE[j][2];
        float x11 = NEG_BIG * (t1 - cM[j][3]) + cE[j][3];
        x00 = x00 > 0.f ? x00 : (expf(x00) - 1.0f);
        x01 = x01 > 0.f ? x01 : (expf(x01) - 1.0f);
        x10 = x10 > 0.f ? x10 : (expf(x10) - 1.0f);
        x11 = x11 > 0.f ? x11 : (expf(x11) - 1.0f);
        float* p0 = out + (size_t)row0 * (HEADS * OUT_F) + head * OUT_F + o0;
        float* p1 = p0 + 8 * (HEADS * OUT_F);
        *(float2*)p0 = make_float2(x00, x01);
        *(float2*)p1 = make_float2(x10, x11);
    }
}

// ---------------------------------------------------------------------------
extern "C" void kernel_launch(void* const* d_in, const int* in_sizes, int n_in,
                              void* d_out, int out_size)
{
    const float* h   = (const float*)d_in[0];   // [4096, 512] f32
    const int*   adj = (const int*)  d_in[1];   // [4096, 4096] i32
    const float* W   = (const float*)d_in[2];   // [8, 512, 64] f32
    const float* a   = (const float*)d_in[3];   // [8, 128, 1] f32
    float*       out = (float*)d_out;           // [4096, 512] f32

    (void)in_sizes; (void)n_in; (void)out_size;

    static bool attr_set = false;
    if (!attr_set) {
        cudaFuncSetAttribute(attn_mma_kernel,
                             cudaFuncAttributeMaxDynamicSharedMemorySize, SMEM_B_BYTES);
        attr_set = true;
    }

    dim3 gA(N_NODES / 64, HEADS);
    wh_kernel<<<gA, 256>>>(h, W, a);

    adjbits_kernel<<<(N_NODES * (N_NODES / 32)) / 256, 256>>>(adj);

    prep_kernel<<<HEADS, 512>>>();

    dim3 gB(N_NODES / 128, HEADS);
    attn_mma_kernel<<<gB, 256, SMEM_B_BYTES>>>(out);
}

// round 5
// speedup vs baseline: 2.5891x; 1.5608x over previous
#include <cuda_runtime.h>
#include <cuda_bf16.h>
#include <math.h>
#include <stdint.h>

#define N_NODES 4096
#define IN_F    512
#define OUT_F   64
#define HEADS   8
#define NEG_BIG (-9000000000000000.0f)

// ---------------- scratch (allocation-free contract) ----------------
__device__ float         g_T  [HEADS * OUT_F];                    // column sums of Wh
// B operands, tiled: element (head, m, o) at ((head*512 + m/8)*64 + o)*8 + m%8
__device__ __nv_bfloat16 g_Bhi[(size_t)HEADS * 512 * 64 * 8];     // 4 MB
__device__ __nv_bfloat16 g_Blo[(size_t)HEADS * 512 * 64 * 8];     // 4 MB
__device__ uint32_t      g_adjbits[(size_t)N_NODES * (N_NODES / 32)]; // 2 MB

// ---------------- helpers ----------------
__device__ __forceinline__ uint32_t smem_to_u32(const void* p) {
    uint32_t a;
    asm("{ .reg .u64 t; cvta.to.shared.u64 t, %1; cvt.u32.u64 %0, t; }" : "=r"(a) : "l"(p));
    return a;
}
__device__ __forceinline__ void ldm4(uint32_t* r, uint32_t addr) {
    asm volatile("ldmatrix.sync.aligned.m8n8.x4.shared.b16 {%0,%1,%2,%3}, [%4];"
        : "=r"(r[0]), "=r"(r[1]), "=r"(r[2]), "=r"(r[3]) : "r"(addr));
}
__device__ __forceinline__ void mma16816(float* c, const uint32_t* a, const uint32_t* b) {
    asm volatile("mma.sync.aligned.m16n8k16.row.col.f32.bf16.bf16.f32 "
        "{%0,%1,%2,%3}, {%4,%5,%6,%7}, {%8,%9}, {%0,%1,%2,%3};"
        : "+f"(c[0]), "+f"(c[1]), "+f"(c[2]), "+f"(c[3])
        : "r"(a[0]), "r"(a[1]), "r"(a[2]), "r"(a[3]), "r"(b[0]), "r"(b[1]));
}
__device__ __forceinline__ uint32_t pack_bf16x2(float lo, float hi) {
    uint32_t d;
    asm("cvt.rn.bf16x2.f32 %0, %1, %2;" : "=r"(d) : "f"(hi), "f"(lo));
    return d;
}
// 2 low bits of x -> packed bf16x2 of {0.0, 1.0}
__device__ __forceinline__ uint32_t expand2(uint32_t x) {
    return ((x & 1u) | ((x << 15) & 0x10000u)) * 0x3F80u;
}

// ---------------------------------------------------------------------------
// Kernel A: Wh = h @ W[head] (fp32), writes bf16 hi/lo tiled B + atomic T.
// Grid (64, 8), 256 threads, 64x64 tile.
// ---------------------------------------------------------------------------
__global__ __launch_bounds__(256) void wh_kernel(const float* __restrict__ h,
                                                 const float* __restrict__ W)
{
    __shared__ float hT[32][68];   // also reused: T partials, hi staging
    __shared__ float wS[32][64];   // also reused: lo staging

    const int t    = threadIdx.x;
    const int tx   = t & 15;
    const int ty   = t >> 4;
    const int n0   = blockIdx.x * 64;
    const int head = blockIdx.y;

    float acc[4][4] = {};
    const float* Wb = W + head * IN_F * OUT_F;

    for (int k0 = 0; k0 < IN_F; k0 += 32) {
        __syncthreads();
        {
            const int r  = t >> 3;
            const int c4 = (t & 7) << 2;
            #pragma unroll
            for (int rb = 0; rb < 64; rb += 32) {
                float4 v = *(const float4*)(h + (size_t)(n0 + r + rb) * IN_F + k0 + c4);
                hT[c4 + 0][r + rb] = v.x;
                hT[c4 + 1][r + rb] = v.y;
                hT[c4 + 2][r + rb] = v.z;
                hT[c4 + 3][r + rb] = v.w;
            }
        }
        {
            const int o4 = tx << 2;
            #pragma unroll
            for (int kb = 0; kb < 32; kb += 16) {
                *(float4*)&wS[ty + kb][o4] =
                    *(const float4*)(Wb + (size_t)(k0 + ty + kb) * OUT_F + o4);
            }
        }
        __syncthreads();
        #pragma unroll
        for (int kk = 0; kk < 32; kk++) {
            float4 av = *(const float4*)&hT[kk][ty << 2];
            float4 bv = *(const float4*)&wS[kk][tx << 2];
            acc[0][0] += av.x * bv.x; acc[0][1] += av.x * bv.y;
            acc[0][2] += av.x * bv.z; acc[0][3] += av.x * bv.w;
            acc[1][0] += av.y * bv.x; acc[1][1] += av.y * bv.y;
            acc[1][2] += av.y * bv.z; acc[1][3] += av.y * bv.w;
            acc[2][0] += av.z * bv.x; acc[2][1] += av.z * bv.y;
            acc[2][2] += av.z * bv.z; acc[2][3] += av.z * bv.w;
            acc[3][0] += av.w * bv.x; acc[3][1] += av.w * bv.y;
            acc[3][2] += av.w * bv.z; acc[3][3] += av.w * bv.w;
        }
    }

    // ---- T partial: per-block column sums -> atomicAdd ----
    __syncthreads();
    float* tred = (float*)hT;   // 16*64 floats
    #pragma unroll
    for (int j = 0; j < 4; j++)
        tred[ty * 64 + (tx << 2) + j] = acc[0][j] + acc[1][j] + acc[2][j] + acc[3][j];
    __syncthreads();
    if (t < 64) {
        float s = 0.f;
        #pragma unroll
        for (int q = 0; q < 16; q++) s += tred[q * 64 + t];
        atomicAdd(&g_T[head * OUT_F + t], s);
    }
    __syncthreads();

    // ---- hi/lo bf16 split, transposed-tiled staging in smem ----
    uint32_t* shi = (uint32_t*)hT;   // 8192 B used
    uint32_t* slo = (uint32_t*)wS;   // 8192 B
    #pragma unroll
    for (int p = 0; p < 2; p++) {
        const int ml = (ty << 2) + 2 * p;          // local m, even
        #pragma unroll
        for (int j = 0; j < 4; j++) {
            const int o = (tx << 2) + j;
            float x0 = acc[2 * p][j], x1 = acc[2 * p + 1][j];
            __nv_bfloat16 h0 = __float2bfloat16(x0);
            __nv_bfloat16 h1 = __float2bfloat16(x1);
            uint32_t hpk = (uint32_t)__bfloat16_as_ushort(h0)
                         | ((uint32_t)__bfloat16_as_ushort(h1) << 16);
            uint32_t lpk = pack_bf16x2(x0 - __bfloat162float(h0),
                                       x1 - __bfloat162float(h1));
            const int L = ((ml >> 3) << 9) + (o << 3) + (ml & 7);  // element index
            shi[L >> 1] = hpk;
            slo[L >> 1] = lpk;
        }
    }
    __syncthreads();
    {
        uint4* dsth = (uint4*)(g_Bhi + ((size_t)head * 512 + (n0 >> 3)) * 512);
        uint4* dstl = (uint4*)(g_Blo + ((size_t)head * 512 + (n0 >> 3)) * 512);
        const uint4* sh4 = (const uint4*)shi;
        const uint4* sl4 = (const uint4*)slo;
        dsth[t]       = sh4[t];
        dsth[t + 256] = sh4[t + 256];
        dstl[t]       = sl4[t];
        dstl[t + 256] = sl4[t + 256];
    }
}

// ---------------------------------------------------------------------------
// Kernel A2: pack adj into bitmask. 524288 words, coalesced.
// ---------------------------------------------------------------------------
__global__ __launch_bounds__(256) void adjbits_kernel(const int* __restrict__ adj)
{
    const size_t idx = (size_t)blockIdx.x * 256 + threadIdx.x;
    const int* p = adj + idx * 32;
    uint32_t w = 0;
    #pragma unroll
    for (int q = 0; q < 8; q++) {
        int4 v = *(const int4*)(p + q * 4);
        w |= (v.x > 0 ? 1u : 0u) << (q * 4 + 0);
        w |= (v.y > 0 ? 1u : 0u) << (q * 4 + 1);
        w |= (v.z > 0 ? 1u : 0u) << (q * 4 + 2);
        w |= (v.w > 0 ? 1u : 0u) << (q * 4 + 3);
    }
    g_adjbits[idx] = w;
}

// ---------------------------------------------------------------------------
// Kernel B v2: out = elu( NEG_BIG * (T[o] - (adj @ (Bhi+Blo))[n,o]) )
// A (0/1 bf16) synthesized in registers from the bitmask; only B goes via smem.
// Block: 128 threads (4 warps), 128n x 64o, one head. Warp: 32n x 64o.
// m-chunk 32, double-buffered B staging, 1 syncthreads/chunk.
// ---------------------------------------------------------------------------
// static smem: [0..256) T floats; buffers at 1024: per-buffer Bhi[64][40] (5120) + Blo (5120)
#define ATTN_SMEM (1024 + 2 * 10240)

__global__ __launch_bounds__(128, 4) void attn_mma2_kernel(float* __restrict__ out)
{
    __shared__ __align__(16) char smem[ATTN_SMEM];
    const uint32_t smem_u = smem_to_u32(smem);
    const int tid  = threadIdx.x;
    const int wid  = tid >> 5;
    const int lane = tid & 31;
    const int n0   = blockIdx.x * 128;
    const int head = blockIdx.y;

    float* tTs = (float*)smem;
    if (tid < 64) tTs[tid] = g_T[head * OUT_F + tid];

    // B staging role: thread -> (o, m-groups sq and sq+2)
    const int so = tid & 63;
    const int sq = tid >> 6;                       // 0/1
    const __nv_bfloat16* bhiH = g_Bhi + (size_t)head * 512 * 512;
    const __nv_bfloat16* bloH = g_Blo + (size_t)head * 512 * 512;
    const uint32_t stsA = (uint32_t)so * 80 + (uint32_t)sq * 16;

    // bitmask rows for this warp's 32 n-rows
    const int nb = n0 + wid * 32;
    const int r  = lane >> 2;
    const uint32_t* bp0 = g_adjbits + (size_t)(nb + r +  0) * 128;
    const uint32_t* bp1 = g_adjbits + (size_t)(nb + r +  8) * 128;
    const uint32_t* bp2 = g_adjbits + (size_t)(nb + r + 16) * 128;
    const uint32_t* bp3 = g_adjbits + (size_t)(nb + r + 24) * 128;

    // ldmatrix B base offset (col-major B fragments, 80B row stride)
    const uint32_t bLd0 = (uint32_t)((lane & 7) + ((lane >> 4) & 1) * 8) * 80
                        + (uint32_t)((lane >> 3) & 1) * 16;

    float cM[2][8][4] = {};

    #define STAGE(CN, BUF) do {                                                  \
        const size_t _g0 = ((size_t)(4 * (CN) + sq) * 64 + so) * 8;              \
        const size_t _g1 = ((size_t)(4 * (CN) + sq + 2) * 64 + so) * 8;          \
        uint4 _h0 = *(const uint4*)(bhiH + _g0);                                 \
        uint4 _h1 = *(const uint4*)(bhiH + _g1);                                 \
        uint4 _l0 = *(const uint4*)(bloH + _g0);                                 \
        uint4 _l1 = *(const uint4*)(bloH + _g1);                                 \
        char* _b = smem + 1024 + (BUF) * 10240;                                  \
        *(uint4*)(_b + stsA)              = _h0;                                 \
        *(uint4*)(_b + stsA + 32)         = _h1;                                 \
        *(uint4*)(_b + 5120 + stsA)       = _l0;                                 \
        *(uint4*)(_b + 5120 + stsA + 32)  = _l1;                                 \
    } while (0)

    STAGE(0, 0);
    __syncthreads();

    for (int c4 = 0; c4 < 32; c4++) {
        const uint4 bw0 = *(const uint4*)(bp0 + c4 * 4);
        const uint4 bw1 = *(const uint4*)(bp1 + c4 * 4);
        const uint4 bw2 = *(const uint4*)(bp2 + c4 * 4);
        const uint4 bw3 = *(const uint4*)(bp3 + c4 * 4);
        #pragma unroll
        for (int cc = 0; cc < 4; cc++) {
            const int c   = c4 * 4 + cc;
            const int cur = c & 1;
            if (c + 1 < 128) STAGE(c + 1, 1 - cur);

            const uint32_t w0 = cc == 0 ? bw0.x : cc == 1 ? bw0.y : cc == 2 ? bw0.z : bw0.w;
            const uint32_t w1 = cc == 0 ? bw1.x : cc == 1 ? bw1.y : cc == 2 ? bw1.z : bw1.w;
            const uint32_t w2 = cc == 0 ? bw2.x : cc == 1 ? bw2.y : cc == 2 ? bw2.z : bw2.w;
            const uint32_t w3 = cc == 0 ? bw3.x : cc == 1 ? bw3.y : cc == 2 ? bw3.z : bw3.w;

            const uint32_t bufB = smem_u + 1024 + (uint32_t)cur * 10240;
            #pragma unroll
            for (int ks = 0; ks < 2; ks++) {
                const int sh = ks * 16 + (lane & 3) * 2;
                uint32_t a0[4], a1[4];
                a0[0] = expand2(w0 >> sh);       a0[1] = expand2(w1 >> sh);
                a0[2] = expand2(w0 >> (sh + 8)); a0[3] = expand2(w1 >> (sh + 8));
                a1[0] = expand2(w2 >> sh);       a1[1] = expand2(w3 >> sh);
                a1[2] = expand2(w2 >> (sh + 8)); a1[3] = expand2(w3 >> (sh + 8));
                #pragma unroll
                for (int g = 0; g < 4; g++) {
                    uint32_t bh[4], bl[4];
                    const uint32_t bo = bLd0 + (uint32_t)g * 1280 + (uint32_t)ks * 32;
                    ldm4(bh, bufB + bo);
                    mma16816(cM[0][2 * g + 0], a0, bh + 0);
                    mma16816(cM[0][2 * g + 1], a0, bh + 2);
                    mma16816(cM[1][2 * g + 0], a1, bh + 0);
                    mma16816(cM[1][2 * g + 1], a1, bh + 2);
                    ldm4(bl, bufB + 5120 + bo);
                    mma16816(cM[0][2 * g + 0], a0, bl + 0);
                    mma16816(cM[0][2 * g + 1], a0, bl + 2);
                    mma16816(cM[1][2 * g + 0], a1, bl + 0);
                    mma16816(cM[1][2 * g + 1], a1, bl + 2);
                }
            }
            __syncthreads();
        }
    }

    // ---- epilogue ----
    const int col0 = (lane & 3) * 2;
    const int rowA = nb + (lane >> 2);
    #pragma unroll
    for (int tt = 0; tt < 2; tt++) {
        const int row = rowA + tt * 16;
        float* p0 = out + (size_t)row * (HEADS * OUT_F) + head * OUT_F;
        float* p1 = p0 + 8 * (HEADS * OUT_F);
        #pragma unroll
        for (int g2 = 0; g2 < 8; g2++) {
            const int o = g2 * 8 + col0;
            const float t0 = tTs[o], t1 = tTs[o + 1];
            float x00 = NEG_BIG * (t0 - cM[tt][g2][0]);
            float x01 = NEG_BIG * (t1 - cM[tt][g2][1]);
            float x10 = NEG_BIG * (t0 - cM[tt][g2][2]);
            float x11 = NEG_BIG * (t1 - cM[tt][g2][3]);
            x00 = x00 > 0.f ? x00 : (expf(x00) - 1.0f);
            x01 = x01 > 0.f ? x01 : (expf(x01) - 1.0f);
            x10 = x10 > 0.f ? x10 : (expf(x10) - 1.0f);
            x11 = x11 > 0.f ? x11 : (expf(x11) - 1.0f);
            *(float2*)(p0 + o) = make_float2(x00, x01);
            *(float2*)(p1 + o) = make_float2(x10, x11);
        }
    }
}

// ---------------------------------------------------------------------------
extern "C" void kernel_launch(void* const* d_in, const int* in_sizes, int n_in,
                              void* d_out, int out_size)
{
    const float* h   = (const float*)d_in[0];   // [4096, 512] f32
    const int*   adj = (const int*)  d_in[1];   // [4096, 4096] i32
    const float* W   = (const float*)d_in[2];   // [8, 512, 64] f32
    float*       out = (float*)d_out;           // [4096, 512] f32

    (void)in_sizes; (void)n_in; (void)out_size;

    static float* tptr = nullptr;
    if (!tptr) cudaGetSymbolAddress((void**)&tptr, g_T);

    cudaMemsetAsync(tptr, 0, HEADS * OUT_F * sizeof(float), 0);

    dim3 gA(N_NODES / 64, HEADS);
    wh_kernel<<<gA, 256>>>(h, W);

    adjbits_kernel<<<(N_NODES * (N_NODES / 32)) / 256, 256>>>(adj);

    dim3 gB(N_NODES / 128, HEADS);
    attn_mma2_kernel<<<gB, 128>>>(out);
}

// round 7
// speedup vs baseline: 2.7316x; 1.0550x over previous
#include <cuda_runtime.h>
#include <cuda_bf16.h>
#include <math.h>
#include <stdint.h>

#define N_NODES 4096
#define IN_F    512
#define OUT_F   64
#define HEADS   8
#define NEG_BIG (-9000000000000000.0f)

// ---------------- scratch (allocation-free contract) ----------------
__device__ float         g_T  [HEADS * OUT_F];                    // column sums of Wh
// B operands, tiled: element (head, m, o) at (head*512 + m/8)*512 + o*8 + m%8
__device__ __nv_bfloat16 g_Bhi[(size_t)HEADS * 512 * 64 * 8];     // 4 MB
__device__ __nv_bfloat16 g_Blo[(size_t)HEADS * 512 * 64 * 8];     // 4 MB
__device__ uint32_t      g_adjbits[(size_t)N_NODES * (N_NODES / 32)]; // 2 MB

// ---------------- helpers ----------------
__device__ __forceinline__ uint32_t smem_to_u32(const void* p) {
    uint32_t a;
    asm("{ .reg .u64 t; cvta.to.shared.u64 t, %1; cvt.u32.u64 %0, t; }" : "=r"(a) : "l"(p));
    return a;
}
__device__ __forceinline__ void ldm4(uint32_t* r, uint32_t addr) {
    asm volatile("ldmatrix.sync.aligned.m8n8.x4.shared.b16 {%0,%1,%2,%3}, [%4];"
        : "=r"(r[0]), "=r"(r[1]), "=r"(r[2]), "=r"(r[3]) : "r"(addr));
}
__device__ __forceinline__ void mma16816(float* c, const uint32_t* a, const uint32_t* b) {
    asm volatile("mma.sync.aligned.m16n8k16.row.col.f32.bf16.bf16.f32 "
        "{%0,%1,%2,%3}, {%4,%5,%6,%7}, {%8,%9}, {%0,%1,%2,%3};"
        : "+f"(c[0]), "+f"(c[1]), "+f"(c[2]), "+f"(c[3])
        : "r"(a[0]), "r"(a[1]), "r"(a[2]), "r"(a[3]), "r"(b[0]), "r"(b[1]));
}
__device__ __forceinline__ uint32_t pack_bf16x2(float lo, float hi) {
    uint32_t d;
    asm("cvt.rn.bf16x2.f32 %0, %1, %2;" : "=r"(d) : "f"(hi), "f"(lo));
    return d;
}
// 2 low bits of x -> packed bf16x2 of {0.0, 1.0}
__device__ __forceinline__ uint32_t expand2(uint32_t x) {
    return ((x & 1u) | ((x << 15) & 0x10000u)) * 0x3F80u;
}

// ---------------------------------------------------------------------------
// Kernel PREP (fused): blocks [0,256) do Wh GEMM + bf16 split + T;
// blocks [256, 2304) pack adj bits. DRAM-bound adj pack overlaps compute.
// ---------------------------------------------------------------------------
#define WH_BLOCKS  256
#define ADJ_BLOCKS 2048
#define PREP_SMEM  33024   // mainloop: hT 16896 + wS 8192; epilogue: shi/slo 32768

__global__ __launch_bounds__(256) void prep_kernel(const float* __restrict__ h,
                                                   const float* __restrict__ W,
                                                   const int* __restrict__ adj)
{
    __shared__ __align__(16) char sm[PREP_SMEM];
    const int t = threadIdx.x;

    if (blockIdx.x >= WH_BLOCKS) {
        // ---- adj bit-packing: 1 word (32 entries) per thread ----
        const size_t idx = (size_t)(blockIdx.x - WH_BLOCKS) * 256 + t;
        const int* p = adj + idx * 32;
        uint32_t w = 0;
        #pragma unroll
        for (int q = 0; q < 8; q++) {
            int4 v = *(const int4*)(p + q * 4);
            w |= (v.x > 0 ? 1u : 0u) << (q * 4 + 0);
            w |= (v.y > 0 ? 1u : 0u) << (q * 4 + 1);
            w |= (v.z > 0 ? 1u : 0u) << (q * 4 + 2);
            w |= (v.w > 0 ? 1u : 0u) << (q * 4 + 3);
        }
        g_adjbits[idx] = w;
        return;
    }

    // ---- Wh GEMM: 128n x 64o tile, 8x4 micro, K-chunk 16, double-buffered ----
    const int n0   = (blockIdx.x & 31) * 128;
    const int head = blockIdx.x >> 5;
    const int tx   = t & 15;         // o-dir: o4 = tx*4
    const int ty   = t >> 4;         // n-dir: rows ty*8 .. ty*8+7

    float (*hT)[132] = (float(*)[132])sm;              // [2*16][132]  ([buf*16+k][n])
    float (*wS)[64]  = (float(*)[64])(sm + 16896);     // [2*16][64]   ([buf*16+k][o])

    const float* Wb = W + head * IN_F * OUT_F;
    const int lr  = t >> 2;          // 0..63 (h-load row; also +64)
    const int lc4 = (t & 3) << 2;    // 0,4,8,12 (h-load k offset)
    const int wk  = t >> 4;          // 0..15 (W-load k)
    const int wo4 = tx << 2;

    float4 ha0, ha1, wv;
    // preload chunk 0
    ha0 = *(const float4*)(h + (size_t)(n0 + lr)      * IN_F + lc4);
    ha1 = *(const float4*)(h + (size_t)(n0 + lr + 64) * IN_F + lc4);
    wv  = *(const float4*)(Wb + (size_t)wk * OUT_F + wo4);
    {
        const float av0[4] = {ha0.x, ha0.y, ha0.z, ha0.w};
        const float av1[4] = {ha1.x, ha1.y, ha1.z, ha1.w};
        #pragma unroll
        for (int j = 0; j < 4; j++) {
            hT[lc4 + j][lr]      = av0[j];
            hT[lc4 + j][lr + 64] = av1[j];
        }
        *(float4*)&wS[wk][wo4] = wv;
    }
    __syncthreads();

    float acc[8][4] = {};

    for (int c = 0; c < 32; c++) {
        const int buf = (c & 1) << 4;
        if (c + 1 < 32) {
            const int k0 = (c + 1) * 16;
            ha0 = *(const float4*)(h + (size_t)(n0 + lr)      * IN_F + k0 + lc4);
            ha1 = *(const float4*)(h + (size_t)(n0 + lr + 64) * IN_F + k0 + lc4);
            wv  = *(const float4*)(Wb + (size_t)(k0 + wk) * OUT_F + wo4);
        }
        #pragma unroll
        for (int kk = 0; kk < 16; kk++) {
            float4 a0 = *(const float4*)&hT[buf + kk][ty << 3];
            float4 a1 = *(const float4*)&hT[buf + kk][(ty << 3) + 4];
            float4 b  = *(const float4*)&wS[buf + kk][tx << 2];
            acc[0][0] += a0.x * b.x; acc[0][1] += a0.x * b.y;
            acc[0][2] += a0.x * b.z; acc[0][3] += a0.x * b.w;
            acc[1][0] += a0.y * b.x; acc[1][1] += a0.y * b.y;
            acc[1][2] += a0.y * b.z; acc[1][3] += a0.y * b.w;
            acc[2][0] += a0.z * b.x; acc[2][1] += a0.z * b.y;
            acc[2][2] += a0.z * b.z; acc[2][3] += a0.z * b.w;
            acc[3][0] += a0.w * b.x; acc[3][1] += a0.w * b.y;
            acc[3][2] += a0.w * b.z; acc[3][3] += a0.w * b.w;
            acc[4][0] += a1.x * b.x; acc[4][1] += a1.x * b.y;
            acc[4][2] += a1.x * b.z; acc[4][3] += a1.x * b.w;
            acc[5][0] += a1.y * b.x; acc[5][1] += a1.y * b.y;
            acc[5][2] += a1.y * b.z; acc[5][3] += a1.y * b.w;
            acc[6][0] += a1.z * b.x; acc[6][1] += a1.z * b.y;
            acc[6][2] += a1.z * b.z; acc[6][3] += a1.z * b.w;
            acc[7][0] += a1.w * b.x; acc[7][1] += a1.w * b.y;
            acc[7][2] += a1.w * b.z; acc[7][3] += a1.w * b.w;
        }
        if (c + 1 < 32) {
            const int nb = ((c + 1) & 1) << 4;
            const float av0[4] = {ha0.x, ha0.y, ha0.z, ha0.w};
            const float av1[4] = {ha1.x, ha1.y, ha1.z, ha1.w};
            #pragma unroll
            for (int j = 0; j < 4; j++) {
                hT[nb + lc4 + j][lr]      = av0[j];
                hT[nb + lc4 + j][lr + 64] = av1[j];
            }
            *(float4*)&wS[nb + wk][wo4] = wv;
        }
        __syncthreads();
    }

    // ---- T partials -> atomicAdd ----
    float* tred = (float*)sm;   // [16][64]
    #pragma unroll
    for (int j = 0; j < 4; j++) {
        float s = 0.f;
        #pragma unroll
        for (int i = 0; i < 8; i++) s += acc[i][j];
        tred[ty * 64 + (tx << 2) + j] = s;
    }
    __syncthreads();
    if (t < 64) {
        float s = 0.f;
        #pragma unroll
        for (int q = 0; q < 16; q++) s += tred[q * 64 + t];
        atomicAdd(&g_T[head * OUT_F + t], s);
    }
    __syncthreads();

    // ---- hi/lo bf16 split into tiled staging ----
    uint32_t* shi = (uint32_t*)sm;              // 16 KB
    uint32_t* slo = (uint32_t*)(sm + 16384);    // 16 KB
    #pragma unroll
    for (int p = 0; p < 4; p++) {
        #pragma unroll
        for (int j = 0; j < 4; j++) {
            const int o = (tx << 2) + j;
            float x0 = acc[2 * p][j], x1 = acc[2 * p + 1][j];
            __nv_bfloat16 h0 = __float2bfloat16(x0);
            __nv_bfloat16 h1 = __float2bfloat16(x1);
            uint32_t hpk = (uint32_t)__bfloat16_as_ushort(h0)
                         | ((uint32_t)__bfloat16_as_ushort(h1) << 16);
            uint32_t lpk = pack_bf16x2(x0 - __bfloat162float(h0),
                                       x1 - __bfloat162float(h1));
            const int idx = ty * 256 + o * 4 + p;   // (group=ty)*256 + o*4 + pair
            shi[idx] = hpk;
            slo[idx] = lpk;
        }
    }
    __syncthreads();
    {
        uint4* dsth = (uint4*)(g_Bhi + ((size_t)head * 512 + (n0 >> 3)) * 512);
        uint4* dstl = (uint4*)(g_Blo + ((size_t)head * 512 + (n0 >> 3)) * 512);
        const uint4* sh4 = (const uint4*)shi;
        const uint4* sl4 = (const uint4*)slo;
        #pragma unroll
        for (int q = 0; q < 4; q++) {
            dsth[t + 256 * q] = sh4[t + 256 * q];
            dstl[t + 256 * q] = sl4[t + 256 * q];
        }
    }
}

// ---------------------------------------------------------------------------
// Kernel B v2 (unchanged, passing in R5):
// out = elu( NEG_BIG * (T[o] - (adj @ (Bhi+Blo))[n,o]) )
// ---------------------------------------------------------------------------
#define ATTN_SMEM (1024 + 2 * 10240)

__global__ __launch_bounds__(128, 4) void attn_mma2_kernel(float* __restrict__ out)
{
    __shared__ __align__(16) char smem[ATTN_SMEM];
    const uint32_t smem_u = smem_to_u32(smem);
    const int tid  = threadIdx.x;
    const int wid  = tid >> 5;
    const int lane = tid & 31;
    const int n0   = blockIdx.x * 128;
    const int head = blockIdx.y;

    float* tTs = (float*)smem;
    if (tid < 64) tTs[tid] = g_T[head * OUT_F + tid];

    const int so = tid & 63;
    const int sq = tid >> 6;
    const __nv_bfloat16* bhiH = g_Bhi + (size_t)head * 512 * 512;
    const __nv_bfloat16* bloH = g_Blo + (size_t)head * 512 * 512;
    const uint32_t stsA = (uint32_t)so * 80 + (uint32_t)sq * 16;

    const int nb = n0 + wid * 32;
    const int r  = lane >> 2;
    const uint32_t* bp0 = g_adjbits + (size_t)(nb + r +  0) * 128;
    const uint32_t* bp1 = g_adjbits + (size_t)(nb + r +  8) * 128;
    const uint32_t* bp2 = g_adjbits + (size_t)(nb + r + 16) * 128;
    const uint32_t* bp3 = g_adjbits + (size_t)(nb + r + 24) * 128;

    const uint32_t bLd0 = (uint32_t)((lane & 7) + ((lane >> 4) & 1) * 8) * 80
                        + (uint32_t)((lane >> 3) & 1) * 16;

    float cM[2][8][4] = {};

    #define STAGE(CN, BUF) do {                                                  \
        const size_t _g0 = ((size_t)(4 * (CN) + sq) * 64 + so) * 8;              \
        const size_t _g1 = ((size_t)(4 * (CN) + sq + 2) * 64 + so) * 8;          \
        uint4 _h0 = *(const uint4*)(bhiH + _g0);                                 \
        uint4 _h1 = *(const uint4*)(bhiH + _g1);                                 \
        uint4 _l0 = *(const uint4*)(bloH + _g0);                                 \
        uint4 _l1 = *(const uint4*)(bloH + _g1);                                 \
        char* _b = smem + 1024 + (BUF) * 10240;                                  \
        *(uint4*)(_b + stsA)              = _h0;                                 \
        *(uint4*)(_b + stsA + 32)         = _h1;                                 \
        *(uint4*)(_b + 5120 + stsA)       = _l0;                                 \
        *(uint4*)(_b + 5120 + stsA + 32)  = _l1;                                 \
    } while (0)

    STAGE(0, 0);
    __syncthreads();

    for (int c4 = 0; c4 < 32; c4++) {
        const uint4 bw0 = *(const uint4*)(bp0 + c4 * 4);
        const uint4 bw1 = *(const uint4*)(bp1 + c4 * 4);
        const uint4 bw2 = *(const uint4*)(bp2 + c4 * 4);
        const uint4 bw3 = *(const uint4*)(bp3 + c4 * 4);
        #pragma unroll
        for (int cc = 0; cc < 4; cc++) {
            const int c   = c4 * 4 + cc;
            const int cur = c & 1;
            if (c + 1 < 128) STAGE(c + 1, 1 - cur);

            const uint32_t w0 = cc == 0 ? bw0.x : cc == 1 ? bw0.y : cc == 2 ? bw0.z : bw0.w;
            const uint32_t w1 = cc == 0 ? bw1.x : cc == 1 ? bw1.y : cc == 2 ? bw1.z : bw1.w;
            const uint32_t w2 = cc == 0 ? bw2.x : cc == 1 ? bw2.y : cc == 2 ? bw2.z : bw2.w;
            const uint32_t w3 = cc == 0 ? bw3.x : cc == 1 ? bw3.y : cc == 2 ? bw3.z : bw3.w;

            const uint32_t bufB = smem_u + 1024 + (uint32_t)cur * 10240;
            #pragma unroll
            for (int ks = 0; ks < 2; ks++) {
                const int sh = ks * 16 + (lane & 3) * 2;
                uint32_t a0[4], a1[4];
                a0[0] = expand2(w0 >> sh);       a0[1] = expand2(w1 >> sh);
                a0[2] = expand2(w0 >> (sh + 8)); a0[3] = expand2(w1 >> (sh + 8));
                a1[0] = expand2(w2 >> sh);       a1[1] = expand2(w3 >> sh);
                a1[2] = expand2(w2 >> (sh + 8)); a1[3] = expand2(w3 >> (sh + 8));
                #pragma unroll
                for (int g = 0; g < 4; g++) {
                    uint32_t bh[4], bl[4];
                    const uint32_t bo = bLd0 + (uint32_t)g * 1280 + (uint32_t)ks * 32;
                    ldm4(bh, bufB + bo);
                    mma16816(cM[0][2 * g + 0], a0, bh + 0);
                    mma16816(cM[0][2 * g + 1], a0, bh + 2);
                    mma16816(cM[1][2 * g + 0], a1, bh + 0);
                    mma16816(cM[1][2 * g + 1], a1, bh + 2);
                    ldm4(bl, bufB + 5120 + bo);
                    mma16816(cM[0][2 * g + 0], a0, bl + 0);
                    mma16816(cM[0][2 * g + 1], a0, bl + 2);
                    mma16816(cM[1][2 * g + 0], a1, bl + 0);
                    mma16816(cM[1][2 * g + 1], a1, bl + 2);
                }
            }
            __syncthreads();
        }
    }

    // ---- epilogue ----
    const int col0 = (lane & 3) * 2;
    const int rowA = nb + (lane >> 2);
    #pragma unroll
    for (int tt = 0; tt < 2; tt++) {
        const int row = rowA + tt * 16;
        float* p0 = out + (size_t)row * (HEADS * OUT_F) + head * OUT_F;
        float* p1 = p0 + 8 * (HEADS * OUT_F);
        #pragma unroll
        for (int g2 = 0; g2 < 8; g2++) {
            const int o = g2 * 8 + col0;
            const float t0 = tTs[o], t1 = tTs[o + 1];
            float x00 = NEG_BIG * (t0 - cM[tt][g2][0]);
            float x01 = NEG_BIG * (t1 - cM[tt][g2][1]);
            float x10 = NEG_BIG * (t0 - cM[tt][g2][2]);
            float x11 = NEG_BIG * (t1 - cM[tt][g2][3]);
            x00 = x00 > 0.f ? x00 : (expf(x00) - 1.0f);
            x01 = x01 > 0.f ? x01 : (expf(x01) - 1.0f);
            x10 = x10 > 0.f ? x10 : (expf(x10) - 1.0f);
            x11 = x11 > 0.f ? x11 : (expf(x11) - 1.0f);
            *(float2*)(p0 + o) = make_float2(x00, x01);
            *(float2*)(p1 + o) = make_float2(x10, x11);
        }
    }
}

// ---------------------------------------------------------------------------
extern "C" void kernel_launch(void* const* d_in, const int* in_sizes, int n_in,
                              void* d_out, int out_size)
{
    const float* h   = (const float*)d_in[0];   // [4096, 512] f32
    const int*   adj = (const int*)  d_in[1];   // [4096, 4096] i32
    const float* W   = (const float*)d_in[2];   // [8, 512, 64] f32
    float*       out = (float*)d_out;           // [4096, 512] f32

    (void)in_sizes; (void)n_in; (void)out_size;

    static float* tptr = nullptr;
    if (!tptr) cudaGetSymbolAddress((void**)&tptr, g_T);

    cudaMemsetAsync(tptr, 0, HEADS * OUT_F * sizeof(float), 0);

    prep_kernel<<<WH_BLOCKS + ADJ_BLOCKS, 256>>>(h, W, adj);

    dim3 gB(N_NODES / 128, HEADS);
    attn_mma2_kernel<<<gB, 128>>>(out);
}

// round 8
// speedup vs baseline: 2.7687x; 1.0136x over previous
#include <cuda_runtime.h>
#include <cuda_bf16.h>
#include <math.h>
#include <stdint.h>

#define N_NODES 4096
#define IN_F    512
#define OUT_F   64
#define HEADS   8
#define NEG_BIG (-9000000000000000.0f)

// ---------------- scratch (allocation-free contract) ----------------
__device__ float         g_T  [HEADS * OUT_F];                    // column sums of Wh
__device__ float         g_M  [(size_t)N_NODES * HEADS * OUT_F];  // 8 MB partial sums
// B operands, tiled: element (head, m, o) at (head*512 + m/8)*512 + o*8 + m%8
__device__ __nv_bfloat16 g_Bhi[(size_t)HEADS * 512 * 64 * 8];     // 4 MB
__device__ __nv_bfloat16 g_Blo[(size_t)HEADS * 512 * 64 * 8];     // 4 MB
__device__ uint32_t      g_adjbits[(size_t)N_NODES * (N_NODES / 32)]; // 2 MB

// ---------------- helpers ----------------
__device__ __forceinline__ uint32_t smem_to_u32(const void* p) {
    uint32_t a;
    asm("{ .reg .u64 t; cvta.to.shared.u64 t, %1; cvt.u32.u64 %0, t; }" : "=r"(a) : "l"(p));
    return a;
}
__device__ __forceinline__ void ldm4(uint32_t* r, uint32_t addr) {
    asm volatile("ldmatrix.sync.aligned.m8n8.x4.shared.b16 {%0,%1,%2,%3}, [%4];"
        : "=r"(r[0]), "=r"(r[1]), "=r"(r[2]), "=r"(r[3]) : "r"(addr));
}
__device__ __forceinline__ void mma16816(float* c, const uint32_t* a, const uint32_t* b) {
    asm volatile("mma.sync.aligned.m16n8k16.row.col.f32.bf16.bf16.f32 "
        "{%0,%1,%2,%3}, {%4,%5,%6,%7}, {%8,%9}, {%0,%1,%2,%3};"
        : "+f"(c[0]), "+f"(c[1]), "+f"(c[2]), "+f"(c[3])
        : "r"(a[0]), "r"(a[1]), "r"(a[2]), "r"(a[3]), "r"(b[0]), "r"(b[1]));
}
__device__ __forceinline__ uint32_t pack_bf16x2(float lo, float hi) {
    uint32_t d;
    asm("cvt.rn.bf16x2.f32 %0, %1, %2;" : "=r"(d) : "f"(hi), "f"(lo));
    return d;
}
// 2 low bits of x -> packed bf16x2 of {0.0, 1.0}
__device__ __forceinline__ uint32_t expand2(uint32_t x) {
    return ((x & 1u) | ((x << 15) & 0x10000u)) * 0x3F80u;
}

// ---------------------------------------------------------------------------
// Kernel PREP (fused, unchanged from R7 passing): blocks [0,256) Wh GEMM;
// blocks [256,2304) adj bit-pack.
// ---------------------------------------------------------------------------
#define WH_BLOCKS  256
#define ADJ_BLOCKS 2048
#define PREP_SMEM  33024

__global__ __launch_bounds__(256) void prep_kernel(const float* __restrict__ h,
                                                   const float* __restrict__ W,
                                                   const int* __restrict__ adj)
{
    __shared__ __align__(16) char sm[PREP_SMEM];
    const int t = threadIdx.x;

    if (blockIdx.x >= WH_BLOCKS) {
        const size_t idx = (size_t)(blockIdx.x - WH_BLOCKS) * 256 + t;
        const int* p = adj + idx * 32;
        uint32_t w = 0;
        #pragma unroll
        for (int q = 0; q < 8; q++) {
            int4 v = *(const int4*)(p + q * 4);
            w |= (v.x > 0 ? 1u : 0u) << (q * 4 + 0);
            w |= (v.y > 0 ? 1u : 0u) << (q * 4 + 1);
            w |= (v.z > 0 ? 1u : 0u) << (q * 4 + 2);
            w |= (v.w > 0 ? 1u : 0u) << (q * 4 + 3);
        }
        g_adjbits[idx] = w;
        return;
    }

    const int n0   = (blockIdx.x & 31) * 128;
    const int head = blockIdx.x >> 5;
    const int tx   = t & 15;
    const int ty   = t >> 4;

    float (*hT)[132] = (float(*)[132])sm;
    float (*wS)[64]  = (float(*)[64])(sm + 16896);

    const float* Wb = W + head * IN_F * OUT_F;
    const int lr  = t >> 2;
    const int lc4 = (t & 3) << 2;
    const int wk  = t >> 4;
    const int wo4 = tx << 2;

    float4 ha0, ha1, wv;
    ha0 = *(const float4*)(h + (size_t)(n0 + lr)      * IN_F + lc4);
    ha1 = *(const float4*)(h + (size_t)(n0 + lr + 64) * IN_F + lc4);
    wv  = *(const float4*)(Wb + (size_t)wk * OUT_F + wo4);
    {
        const float av0[4] = {ha0.x, ha0.y, ha0.z, ha0.w};
        const float av1[4] = {ha1.x, ha1.y, ha1.z, ha1.w};
        #pragma unroll
        for (int j = 0; j < 4; j++) {
            hT[lc4 + j][lr]      = av0[j];
            hT[lc4 + j][lr + 64] = av1[j];
        }
        *(float4*)&wS[wk][wo4] = wv;
    }
    __syncthreads();

    float acc[8][4] = {};

    for (int c = 0; c < 32; c++) {
        const int buf = (c & 1) << 4;
        if (c + 1 < 32) {
            const int k0 = (c + 1) * 16;
            ha0 = *(const float4*)(h + (size_t)(n0 + lr)      * IN_F + k0 + lc4);
            ha1 = *(const float4*)(h + (size_t)(n0 + lr + 64) * IN_F + k0 + lc4);
            wv  = *(const float4*)(Wb + (size_t)(k0 + wk) * OUT_F + wo4);
        }
        #pragma unroll
        for (int kk = 0; kk < 16; kk++) {
            float4 a0 = *(const float4*)&hT[buf + kk][ty << 3];
            float4 a1 = *(const float4*)&hT[buf + kk][(ty << 3) + 4];
            float4 b  = *(const float4*)&wS[buf + kk][tx << 2];
            acc[0][0] += a0.x * b.x; acc[0][1] += a0.x * b.y;
            acc[0][2] += a0.x * b.z; acc[0][3] += a0.x * b.w;
            acc[1][0] += a0.y * b.x; acc[1][1] += a0.y * b.y;
            acc[1][2] += a0.y * b.z; acc[1][3] += a0.y * b.w;
            acc[2][0] += a0.z * b.x; acc[2][1] += a0.z * b.y;
            acc[2][2] += a0.z * b.z; acc[2][3] += a0.z * b.w;
            acc[3][0] += a0.w * b.x; acc[3][1] += a0.w * b.y;
            acc[3][2] += a0.w * b.z; acc[3][3] += a0.w * b.w;
            acc[4][0] += a1.x * b.x; acc[4][1] += a1.x * b.y;
            acc[4][2] += a1.x * b.z; acc[4][3] += a1.x * b.w;
            acc[5][0] += a1.y * b.x; acc[5][1] += a1.y * b.y;
            acc[5][2] += a1.y * b.z; acc[5][3] += a1.y * b.w;
            acc[6][0] += a1.z * b.x; acc[6][1] += a1.z * b.y;
            acc[6][2] += a1.z * b.z; acc[6][3] += a1.z * b.w;
            acc[7][0] += a1.w * b.x; acc[7][1] += a1.w * b.y;
            acc[7][2] += a1.w * b.z; acc[7][3] += a1.w * b.w;
        }
        if (c + 1 < 32) {
            const int nb = ((c + 1) & 1) << 4;
            const float av0[4] = {ha0.x, ha0.y, ha0.z, ha0.w};
            const float av1[4] = {ha1.x, ha1.y, ha1.z, ha1.w};
            #pragma unroll
            for (int j = 0; j < 4; j++) {
                hT[nb + lc4 + j][lr]      = av0[j];
                hT[nb + lc4 + j][lr + 64] = av1[j];
            }
            *(float4*)&wS[nb + wk][wo4] = wv;
        }
        __syncthreads();
    }

    // ---- T partials -> atomicAdd ----
    float* tred = (float*)sm;
    #pragma unroll
    for (int j = 0; j < 4; j++) {
        float s = 0.f;
        #pragma unroll
        for (int i = 0; i < 8; i++) s += acc[i][j];
        tred[ty * 64 + (tx << 2) + j] = s;
    }
    __syncthreads();
    if (t < 64) {
        float s = 0.f;
        #pragma unroll
        for (int q = 0; q < 16; q++) s += tred[q * 64 + t];
        atomicAdd(&g_T[head * OUT_F + t], s);
    }
    __syncthreads();

    // ---- hi/lo bf16 split into tiled staging ----
    uint32_t* shi = (uint32_t*)sm;
    uint32_t* slo = (uint32_t*)(sm + 16384);
    #pragma unroll
    for (int p = 0; p < 4; p++) {
        #pragma unroll
        for (int j = 0; j < 4; j++) {
            const int o = (tx << 2) + j;
            float x0 = acc[2 * p][j], x1 = acc[2 * p + 1][j];
            __nv_bfloat16 h0 = __float2bfloat16(x0);
            __nv_bfloat16 h1 = __float2bfloat16(x1);
            uint32_t hpk = (uint32_t)__bfloat16_as_ushort(h0)
                         | ((uint32_t)__bfloat16_as_ushort(h1) << 16);
            uint32_t lpk = pack_bf16x2(x0 - __bfloat162float(h0),
                                       x1 - __bfloat162float(h1));
            const int idx = ty * 256 + o * 4 + p;
            shi[idx] = hpk;
            slo[idx] = lpk;
        }
    }
    __syncthreads();
    {
        uint4* dsth = (uint4*)(g_Bhi + ((size_t)head * 512 + (n0 >> 3)) * 512);
        uint4* dstl = (uint4*)(g_Blo + ((size_t)head * 512 + (n0 >> 3)) * 512);
        const uint4* sh4 = (const uint4*)shi;
        const uint4* sl4 = (const uint4*)slo;
        #pragma unroll
        for (int q = 0; q < 4; q++) {
            dsth[t + 256 * q] = sh4[t + 256 * q];
            dstl[t + 256 * q] = sl4[t + 256 * q];
        }
    }
}

// ---------------------------------------------------------------------------
// Kernel B v3: K-split masked aggregation.
// Grid (64, 8): x = n-tile (0..31) | khalf<<5; y = head.
// Each block: 128n x 64o x 2048m partial of M = adj @ (Bhi+Blo), f32 regs,
// atomicAdd into g_M. Structure identical to proven v2, half the chunks.
// ---------------------------------------------------------------------------
#define ATTN_SMEM (1024 + 2 * 10240)

__global__ __launch_bounds__(128, 4) void attn_mma3_kernel()
{
    __shared__ __align__(16) char smem[ATTN_SMEM];
    const uint32_t smem_u = smem_to_u32(smem);
    const int tid  = threadIdx.x;
    const int wid  = tid >> 5;
    const int lane = tid & 31;
    const int n0   = (blockIdx.x & 31) * 128;
    const int kh   = blockIdx.x >> 5;          // 0/1 K-half
    const int head = blockIdx.y;

    const int so = tid & 63;
    const int sq = tid >> 6;
    const __nv_bfloat16* bhiH = g_Bhi + (size_t)head * 512 * 512;
    const __nv_bfloat16* bloH = g_Blo + (size_t)head * 512 * 512;
    const uint32_t stsA = (uint32_t)so * 80 + (uint32_t)sq * 16;
    const int kgbase = kh * 256;               // m-group base (2048/8)

    const int nb = n0 + wid * 32;
    const int r  = lane >> 2;
    const uint32_t* bp0 = g_adjbits + (size_t)(nb + r +  0) * 128 + kh * 64;
    const uint32_t* bp1 = g_adjbits + (size_t)(nb + r +  8) * 128 + kh * 64;
    const uint32_t* bp2 = g_adjbits + (size_t)(nb + r + 16) * 128 + kh * 64;
    const uint32_t* bp3 = g_adjbits + (size_t)(nb + r + 24) * 128 + kh * 64;

    const uint32_t bLd0 = (uint32_t)((lane & 7) + ((lane >> 4) & 1) * 8) * 80
                        + (uint32_t)((lane >> 3) & 1) * 16;

    float cM[2][8][4] = {};

    #define STAGE(CN, BUF) do {                                                  \
        const size_t _g0 = ((size_t)(kgbase + 4 * (CN) + sq) * 64 + so) * 8;     \
        const size_t _g1 = ((size_t)(kgbase + 4 * (CN) + sq + 2) * 64 + so) * 8; \
        uint4 _h0 = *(const uint4*)(bhiH + _g0);                                 \
        uint4 _h1 = *(const uint4*)(bhiH + _g1);                                 \
        uint4 _l0 = *(const uint4*)(bloH + _g0);                                 \
        uint4 _l1 = *(const uint4*)(bloH + _g1);                                 \
        char* _b = smem + 1024 + (BUF) * 10240;                                  \
        *(uint4*)(_b + stsA)              = _h0;                                 \
        *(uint4*)(_b + stsA + 32)         = _h1;                                 \
        *(uint4*)(_b + 5120 + stsA)       = _l0;                                 \
        *(uint4*)(_b + 5120 + stsA + 32)  = _l1;                                 \
    } while (0)

    STAGE(0, 0);
    __syncthreads();

    for (int c4 = 0; c4 < 16; c4++) {
        const uint4 bw0 = *(const uint4*)(bp0 + c4 * 4);
        const uint4 bw1 = *(const uint4*)(bp1 + c4 * 4);
        const uint4 bw2 = *(const uint4*)(bp2 + c4 * 4);
        const uint4 bw3 = *(const uint4*)(bp3 + c4 * 4);
        #pragma unroll
        for (int cc = 0; cc < 4; cc++) {
            const int c   = c4 * 4 + cc;
            const int cur = c & 1;
            if (c + 1 < 64) STAGE(c + 1, 1 - cur);

            const uint32_t w0 = cc == 0 ? bw0.x : cc == 1 ? bw0.y : cc == 2 ? bw0.z : bw0.w;
            const uint32_t w1 = cc == 0 ? bw1.x : cc == 1 ? bw1.y : cc == 2 ? bw1.z : bw1.w;
            const uint32_t w2 = cc == 0 ? bw2.x : cc == 1 ? bw2.y : cc == 2 ? bw2.z : bw2.w;
            const uint32_t w3 = cc == 0 ? bw3.x : cc == 1 ? bw3.y : cc == 2 ? bw3.z : bw3.w;

            const uint32_t bufB = smem_u + 1024 + (uint32_t)cur * 10240;
            #pragma unroll
            for (int ks = 0; ks < 2; ks++) {
                const int sh = ks * 16 + (lane & 3) * 2;
                uint32_t a0[4], a1[4];
                a0[0] = expand2(w0 >> sh);       a0[1] = expand2(w1 >> sh);
                a0[2] = expand2(w0 >> (sh + 8)); a0[3] = expand2(w1 >> (sh + 8));
                a1[0] = expand2(w2 >> sh);       a1[1] = expand2(w3 >> sh);
                a1[2] = expand2(w2 >> (sh + 8)); a1[3] = expand2(w3 >> (sh + 8));
                #pragma unroll
                for (int g = 0; g < 4; g++) {
                    uint32_t bh[4], bl[4];
                    const uint32_t bo = bLd0 + (uint32_t)g * 1280 + (uint32_t)ks * 32;
                    ldm4(bh, bufB + bo);
                    mma16816(cM[0][2 * g + 0], a0, bh + 0);
                    mma16816(cM[0][2 * g + 1], a0, bh + 2);
                    mma16816(cM[1][2 * g + 0], a1, bh + 0);
                    mma16816(cM[1][2 * g + 1], a1, bh + 2);
                    ldm4(bl, bufB + 5120 + bo);
                    mma16816(cM[0][2 * g + 0], a0, bl + 0);
                    mma16816(cM[0][2 * g + 1], a0, bl + 2);
                    mma16816(cM[1][2 * g + 0], a1, bl + 0);
                    mma16816(cM[1][2 * g + 1], a1, bl + 2);
                }
            }
            __syncthreads();
        }
    }

    // ---- epilogue: atomicAdd partial M ----
    const int col0 = (lane & 3) * 2;
    const int rowA = nb + (lane >> 2);
    #pragma unroll
    for (int tt = 0; tt < 2; tt++) {
        float* p0 = g_M + (size_t)(rowA + tt * 16) * (HEADS * OUT_F) + head * OUT_F;
        float* p1 = p0 + 8 * (HEADS * OUT_F);
        #pragma unroll
        for (int g2 = 0; g2 < 8; g2++) {
            const int o = g2 * 8 + col0;
            atomicAdd(p0 + o,     cM[tt][g2][0]);
            atomicAdd(p0 + o + 1, cM[tt][g2][1]);
            atomicAdd(p1 + o,     cM[tt][g2][2]);
            atomicAdd(p1 + o + 1, cM[tt][g2][3]);
        }
    }
}

// ---------------------------------------------------------------------------
// Fixup: out = elu( NEG_BIG * (T[col] - M) ), vectorized float4.
// 2M elements -> 524288 float4 -> 2048 blocks x 256.
// ---------------------------------------------------------------------------
__global__ __launch_bounds__(256) void fixup_kernel(float* __restrict__ out)
{
    const int idx  = blockIdx.x * 256 + threadIdx.x;
    const int col  = (idx << 2) & 511;          // head*64 + o
    float4 m = *(const float4*)(g_M + (size_t)idx * 4);
    float4 tv = *(const float4*)(g_T + col);
    float x0 = NEG_BIG * (tv.x - m.x);
    float x1 = NEG_BIG * (tv.y - m.y);
    float x2 = NEG_BIG * (tv.z - m.z);
    float x3 = NEG_BIG * (tv.w - m.w);
    x0 = x0 > 0.f ? x0 : (expf(x0) - 1.0f);
    x1 = x1 > 0.f ? x1 : (expf(x1) - 1.0f);
    x2 = x2 > 0.f ? x2 : (expf(x2) - 1.0f);
    x3 = x3 > 0.f ? x3 : (expf(x3) - 1.0f);
    *(float4*)(out + (size_t)idx * 4) = make_float4(x0, x1, x2, x3);
}

// ---------------------------------------------------------------------------
extern "C" void kernel_launch(void* const* d_in, const int* in_sizes, int n_in,
                              void* d_out, int out_size)
{
    const float* h   = (const float*)d_in[0];   // [4096, 512] f32
    const int*   adj = (const int*)  d_in[1];   // [4096, 4096] i32
    const float* W   = (const float*)d_in[2];   // [8, 512, 64] f32
    float*       out = (float*)d_out;           // [4096, 512] f32

    (void)in_sizes; (void)n_in; (void)out_size;

    static float* tptr = nullptr;
    static float* mptr = nullptr;
    if (!tptr) cudaGetSymbolAddress((void**)&tptr, g_T);
    if (!mptr) cudaGetSymbolAddress((void**)&mptr, g_M);

    cudaMemsetAsync(tptr, 0, HEADS * OUT_F * sizeof(float), 0);
    cudaMemsetAsync(mptr, 0, (size_t)N_NODES * HEADS * OUT_F * sizeof(float), 0);

    prep_kernel<<<WH_BLOCKS + ADJ_BLOCKS, 256>>>(h, W, adj);

    dim3 gB(64, HEADS);
    attn_mma3_kernel<<<gB, 128>>>();

    fixup_kernel<<<(N_NODES * HEADS * OUT_F / 4) / 256, 256>>>(out);
}